// round 15
// baseline (speedup 1.0000x reference)
#include <cuda_runtime.h>
#include <cstdint>

#define N_NODES 65536
#define N_EDGES 524288
#define NGRAPH  64

// ---------------- device scratch (zero-initialized at module load) ----------------
__device__ int   g_count[N_NODES];
__device__ int   g_fill[N_NODES];
__device__ int   g_rowptr[N_NODES + 1];
__device__ int   g_ssrc[N_EDGES];
__device__ __align__(16) float g_scoef[(size_t)N_EDGES * 12];
__device__ __align__(16) float g_cat0[(size_t)N_NODES * 128];      // [h3 | h2]
__device__ __align__(16) float g_cat1[(size_t)N_NODES * 96];       // [h4 | h1]
__device__ __align__(16) float g_h5[(size_t)N_NODES * 32];
__device__ __align__(16) float g_part[(size_t)256 * NGRAPH * 128];
// cached phase-1 aggregations (linear op on shared edge structure):
__device__ __align__(16) float g_Yh1[(size_t)N_NODES * 288];       // enc1's Y (9 x 32), reused by dec1
__device__ __align__(16) float g_Yh2[(size_t)N_NODES * 576];       // enc2's Y (9 x 64), reused by dec0

// ---------------- packed f32x2 FMA (sm_103a FFMA2) ----------------
__device__ __forceinline__ float2 ffma2(float2 a, float2 b, float2 c) {
    float2 d;
    asm("fma.rn.f32x2 %0, %1, %2, %3;"
        : "=l"(*reinterpret_cast<unsigned long long*>(&d))
        : "l"(*reinterpret_cast<unsigned long long*>(&a)),
          "l"(*reinterpret_cast<unsigned long long*>(&b)),
          "l"(*reinterpret_cast<unsigned long long*>(&c)));
    return d;
}

// ---------------- CSR build ----------------
__global__ void count_kernel(const int* __restrict__ ei) {
    int e = blockIdx.x * blockDim.x + threadIdx.x;
    if (e < N_EDGES) {
        int dst = ei[N_EDGES + e];
        if ((unsigned)dst < (unsigned)N_NODES) atomicAdd(&g_count[dst], 1);
    }
}

__global__ void scan_kernel() {
    __shared__ int ssum[1024];
    int t = threadIdx.x;
    int base = t * 64;
    int sum = 0;
    for (int j = 0; j < 64; ++j) sum += g_count[base + j];
    ssum[t] = sum;
    __syncthreads();
    for (int off = 1; off < 1024; off <<= 1) {
        int v = (t >= off) ? ssum[t - off] : 0;
        __syncthreads();
        ssum[t] += v;
        __syncthreads();
    }
    int run = ssum[t] - sum;
    for (int j = 0; j < 64; ++j) { g_rowptr[base + j] = run; run += g_count[base + j]; }
    if (t == 1023) g_rowptr[N_NODES] = run;
}

__global__ void fill_kernel(const int* __restrict__ ei, const float* __restrict__ pos) {
    int e = blockIdx.x * blockDim.x + threadIdx.x;
    if (e >= N_EDGES) return;
    int src = ei[e];
    int dst = ei[N_EDGES + e];
    if ((unsigned)src >= (unsigned)N_NODES || (unsigned)dst >= (unsigned)N_NODES) return;
    float p0 = pos[2 * e], p1 = pos[2 * e + 1];
    int   b0i = (int)floorf(p0);
    int   b1i = (int)floorf(p1);
    float f0 = p0 - (float)b0i;
    float f1 = p1 - (float)b1i;
    float ba[3] = {0.5f * (1.f - f0) * (1.f - f0), -f0 * f0 + f0 + 0.5f, 0.5f * f0 * f0};
    float bb[3] = {0.5f * (1.f - f1) * (1.f - f1), -f1 * f1 + f1 + 0.5f, 0.5f * f1 * f1};
    int ia[3], ib[3];
#pragma unroll
    for (int t = 0; t < 3; ++t) {
        ia[t] = min(max(b0i + t, 0), 2);
        ib[t] = min(max(b1i + t, 0), 2);
    }
    float ck[9];
#pragma unroll
    for (int k = 0; k < 9; ++k) ck[k] = 0.f;
#pragma unroll
    for (int i = 0; i < 3; ++i)
#pragma unroll
        for (int j = 0; j < 3; ++j)
            ck[ia[i] + 3 * ib[j]] += ba[i] * bb[j];

    int slot = g_rowptr[dst] + atomicAdd(&g_fill[dst], 1);
    g_ssrc[slot] = src;
    float* cw = g_scoef + (size_t)slot * 12;
#pragma unroll
    for (int k = 0; k < 9; ++k) cw[k] = ck[k];
    cw[9] = 0.f; cw[10] = 0.f; cw[11] = 0.f;
}

// ---------------- fused SplineConv layer (8 nodes/block) ----------------
// Phase 1: warp per node; aggregate only CIAGG channels (decoders reuse cached Y for the
//          concat-tail); EPW edges concurrently via lane-groups; FFMA2 accumulate;
//          shfl butterfly; enc1/enc2 also persist Y to global for decoder reuse.
// Phase 2: warp-split-K GEMM (broadcast smem y, L2-stream weights, packed FFMA2).
template <int CI, int CO, int LAYER>
__launch_bounds__(256)
__global__ void spline_conv_kernel(const float* __restrict__ xext,
                                   const float* __restrict__ W,     // [9*CI][CO]
                                   const float* __restrict__ root,  // [CI][CO]
                                   const float* __restrict__ bias)  // [CO]
{
    constexpr int KT    = 9 * CI;
    constexpr int CIAGG = (LAYER >= 3) ? 64 : CI;    // decoders aggregate first 64 ch only
    constexpr int LPE   = CIAGG / 4;                 // lanes per edge: 4,8,16,16,16
    constexpr int EPW   = 32 / LPE;                  // edges per warp-iter: 8,4,2,2,2
    constexpr int SMAX  = (8 * KT > 64 * CO) ? 8 * KT : 64 * CO;

    const float* xin; float* xout; int istride, ostride;
    if constexpr (LAYER == 0)      { xin = xext;        istride = 16;  xout = g_cat1 + 64; ostride = 96;  }
    else if constexpr (LAYER == 1) { xin = g_cat1 + 64; istride = 96;  xout = g_cat0 + 64; ostride = 128; }
    else if constexpr (LAYER == 2) { xin = g_cat0 + 64; istride = 128; xout = g_cat0;      ostride = 128; }
    else if constexpr (LAYER == 3) { xin = g_cat0;      istride = 128; xout = g_cat1;      ostride = 96;  }
    else                           { xin = g_cat1;      istride = 96;  xout = g_h5;        ostride = 32;  }

    __shared__ __align__(16) float smem[SMAX + 8 * CI];
    float* Ys = smem;             // [8][KT]  (later overlaid by reduction buffer)
    float* Xs = smem + SMAX;      // [8][CI]

    int tid = threadIdx.x, lane = tid & 31, warp = tid >> 5;
    int nbase = blockIdx.x * 8;

    // Re-zero CSR scratch for the next run (dead after fill_kernel this run).
    if constexpr (LAYER == 0) {
        if (tid < 8) { g_count[nbase + tid] = 0; g_fill[nbase + tid] = 0; }
    }

    // ---- phase 1 ----
    {
        int n = nbase + warp;
        int s0 = g_rowptr[n], s1 = g_rowptr[n + 1];
        int deg = s1 - s0;
        int i_ch = lane % LPE;           // channel chunk (float4 index) within aggregated part
        int g    = lane / LPE;           // edge sub-slot
        bool active = (g < EPW) && (4 * i_ch < CIAGG);

        float2 accp[9][2];
#pragma unroll
        for (int k = 0; k < 9; ++k) {
            accp[k][0] = make_float2(0.f, 0.f);
            accp[k][1] = make_float2(0.f, 0.f);
        }

        int nit = (deg + EPW - 1) / EPW;

        float4 caB[2], cbB[2], ccB[2], xvB[2];
        bool   vB[2];
        auto LD = [&](int t, int b) {
            int s = s0 + t * EPW + g;
            bool ok = active && (s < s1);
            vB[b] = ok;
            if (ok) {
                int src = g_ssrc[s];
                const float4* cp = reinterpret_cast<const float4*>(g_scoef + (size_t)s * 12);
                caB[b] = cp[0]; cbB[b] = cp[1]; ccB[b] = cp[2];
                xvB[b] = *reinterpret_cast<const float4*>(xin + (size_t)src * istride + 4 * i_ch);
            }
        };
        if (nit > 0) LD(0, 0);
        if (nit > 1) LD(1, 1);
        for (int t = 0; t < nit; ++t) {
            int b = t & 1;
            float4 A = caB[b], Bc = cbB[b], C = ccB[b], X = xvB[b];
            bool ok = vB[b];
            if (t + 2 < nit) LD(t + 2, b);
            if (ok) {
                float c9[9] = {A.x, A.y, A.z, A.w, Bc.x, Bc.y, Bc.z, Bc.w, C.x};
                float2 xlo = make_float2(X.x, X.y);
                float2 xhi = make_float2(X.z, X.w);
#pragma unroll
                for (int k = 0; k < 9; ++k) {
                    float2 cc = make_float2(c9[k], c9[k]);
                    accp[k][0] = ffma2(cc, xlo, accp[k][0]);
                    accp[k][1] = ffma2(cc, xhi, accp[k][1]);
                }
            }
        }

        // cross-group butterfly (sum over edge sub-slots)
        if constexpr (EPW > 1) {
#pragma unroll
            for (int m = LPE; m < 32; m <<= 1)
#pragma unroll
                for (int k = 0; k < 9; ++k)
#pragma unroll
                    for (int h = 0; h < 2; ++h) {
                        accp[k][h].x += __shfl_xor_sync(0xffffffffu, accp[k][h].x, m);
                        accp[k][h].y += __shfl_xor_sync(0xffffffffu, accp[k][h].y, m);
                    }
        }

        float inv = 1.0f / (float)max(1, deg);
        if (g == 0 && 4 * i_ch < CIAGG) {
#pragma unroll
            for (int k = 0; k < 9; ++k) {
                float4 yv = make_float4(accp[k][0].x * inv, accp[k][0].y * inv,
                                        accp[k][1].x * inv, accp[k][1].y * inv);
                *reinterpret_cast<float4*>(&Ys[warp * KT + k * CI + 4 * i_ch]) = yv;
                if constexpr (LAYER == 1)
                    *reinterpret_cast<float4*>(&g_Yh1[(size_t)n * 288 + k * 32 + 4 * i_ch]) = yv;
                if constexpr (LAYER == 2)
                    *reinterpret_cast<float4*>(&g_Yh2[(size_t)n * 576 + k * 64 + 4 * i_ch]) = yv;
            }
        }
        // decoders: stream cached aggregation into the concat-tail channels of Ys
        if constexpr (LAYER == 3) {          // tail = h2's Y (64 ch) from enc2
            for (int idx = lane; idx < 144; idx += 32) {       // 9 * 64 / 4
                int k = idx >> 4, cq = idx & 15;
                float4 v = *reinterpret_cast<const float4*>(&g_Yh2[(size_t)n * 576 + k * 64 + 4 * cq]);
                *reinterpret_cast<float4*>(&Ys[warp * KT + k * CI + 64 + 4 * cq]) = v;
            }
        }
        if constexpr (LAYER == 4) {          // tail = h1's Y (32 ch) from enc1
            for (int idx = lane; idx < 72; idx += 32) {        // 9 * 32 / 4
                int k = idx >> 3, cq = idx & 7;
                float4 v = *reinterpret_cast<const float4*>(&g_Yh1[(size_t)n * 288 + k * 32 + 4 * cq]);
                *reinterpret_cast<float4*>(&Ys[warp * KT + k * CI + 64 + 4 * cq]) = v;
            }
        }
        if (4 * lane < CI)
            *reinterpret_cast<float4*>(&Xs[warp * CI + 4 * lane]) =
                *reinterpret_cast<const float4*>(xin + (size_t)n * istride + 4 * lane);
    }
    __syncthreads();

    // ---- phase 2: warp-split-K GEMM (measured-best R10 form) ----
    if constexpr (CO == 64) {
        float2 acc2[8];
#pragma unroll
        for (int r = 0; r < 8; ++r) acc2[r] = make_float2(0.f, 0.f);

#pragma unroll 2
        for (int p4 = warp; p4 < KT / 4; p4 += 8) {
            int k = 4 * p4;
            float wA[4], wB[4];
#pragma unroll
            for (int i = 0; i < 4; ++i) {
                wA[i] = __ldg(W + (size_t)(k + i) * CO + lane);
                wB[i] = __ldg(W + (size_t)(k + i) * CO + lane + 32);
            }
#pragma unroll
            for (int r = 0; r < 8; ++r) {
                float4 y = *reinterpret_cast<const float4*>(&Ys[r * KT + k]);
                acc2[r] = ffma2(make_float2(y.x, y.x), make_float2(wA[0], wB[0]), acc2[r]);
                acc2[r] = ffma2(make_float2(y.y, y.y), make_float2(wA[1], wB[1]), acc2[r]);
                acc2[r] = ffma2(make_float2(y.z, y.z), make_float2(wA[2], wB[2]), acc2[r]);
                acc2[r] = ffma2(make_float2(y.w, y.w), make_float2(wA[3], wB[3]), acc2[r]);
            }
        }
#pragma unroll 2
        for (int p4 = warp; p4 < CI / 4; p4 += 8) {
            int k = 4 * p4;
            float wA[4], wB[4];
#pragma unroll
            for (int i = 0; i < 4; ++i) {
                wA[i] = __ldg(root + (size_t)(k + i) * CO + lane);
                wB[i] = __ldg(root + (size_t)(k + i) * CO + lane + 32);
            }
#pragma unroll
            for (int r = 0; r < 8; ++r) {
                float4 y = *reinterpret_cast<const float4*>(&Xs[r * CI + k]);
                acc2[r] = ffma2(make_float2(y.x, y.x), make_float2(wA[0], wB[0]), acc2[r]);
                acc2[r] = ffma2(make_float2(y.y, y.y), make_float2(wA[1], wB[1]), acc2[r]);
                acc2[r] = ffma2(make_float2(y.z, y.z), make_float2(wA[2], wB[2]), acc2[r]);
                acc2[r] = ffma2(make_float2(y.w, y.w), make_float2(wA[3], wB[3]), acc2[r]);
            }
        }
        __syncthreads();
        float* red = smem;   // [8 warps][8 rows][CO]
#pragma unroll
        for (int r = 0; r < 8; ++r) {
            red[(warp * 8 + r) * CO + lane]      = acc2[r].x;
            red[(warp * 8 + r) * CO + lane + 32] = acc2[r].y;
        }
        __syncthreads();
        int r = warp;
        float vA = __ldg(bias + lane), vB = __ldg(bias + lane + 32);
#pragma unroll
        for (int w = 0; w < 8; ++w) {
            vA += red[(w * 8 + r) * CO + lane];
            vB += red[(w * 8 + r) * CO + lane + 32];
        }
        vA = fminf(fmaxf(vA, 0.f), 6.f);
        vB = fminf(fmaxf(vB, 0.f), 6.f);
        xout[(size_t)(nbase + r) * ostride + lane]      = vA;
        xout[(size_t)(nbase + r) * ostride + lane + 32] = vB;
    } else {  // CO == 32
        float2 acc2[4];
#pragma unroll
        for (int j = 0; j < 4; ++j) acc2[j] = make_float2(0.f, 0.f);

#pragma unroll 2
        for (int p4 = warp; p4 < KT / 4; p4 += 8) {
            int k = 4 * p4;
            float w4[4];
#pragma unroll
            for (int i = 0; i < 4; ++i) w4[i] = __ldg(W + (size_t)(k + i) * CO + lane);
#pragma unroll
            for (int j = 0; j < 4; ++j) {
                float4 ya = *reinterpret_cast<const float4*>(&Ys[(2 * j) * KT + k]);
                float4 yb = *reinterpret_cast<const float4*>(&Ys[(2 * j + 1) * KT + k]);
                acc2[j] = ffma2(make_float2(ya.x, yb.x), make_float2(w4[0], w4[0]), acc2[j]);
                acc2[j] = ffma2(make_float2(ya.y, yb.y), make_float2(w4[1], w4[1]), acc2[j]);
                acc2[j] = ffma2(make_float2(ya.z, yb.z), make_float2(w4[2], w4[2]), acc2[j]);
                acc2[j] = ffma2(make_float2(ya.w, yb.w), make_float2(w4[3], w4[3]), acc2[j]);
            }
        }
#pragma unroll 2
        for (int p4 = warp; p4 < CI / 4; p4 += 8) {
            int k = 4 * p4;
            float w4[4];
#pragma unroll
            for (int i = 0; i < 4; ++i) w4[i] = __ldg(root + (size_t)(k + i) * CO + lane);
#pragma unroll
            for (int j = 0; j < 4; ++j) {
                float4 ya = *reinterpret_cast<const float4*>(&Xs[(2 * j) * CI + k]);
                float4 yb = *reinterpret_cast<const float4*>(&Xs[(2 * j + 1) * CI + k]);
                acc2[j] = ffma2(make_float2(ya.x, yb.x), make_float2(w4[0], w4[0]), acc2[j]);
                acc2[j] = ffma2(make_float2(ya.y, yb.y), make_float2(w4[1], w4[1]), acc2[j]);
                acc2[j] = ffma2(make_float2(ya.z, yb.z), make_float2(w4[2], w4[2]), acc2[j]);
                acc2[j] = ffma2(make_float2(ya.w, yb.w), make_float2(w4[3], w4[3]), acc2[j]);
            }
        }
        __syncthreads();
        float* red = smem;   // [8 warps][8 rows][CO]
#pragma unroll
        for (int j = 0; j < 4; ++j) {
            red[(warp * 8 + 2 * j) * CO + lane]     = acc2[j].x;
            red[(warp * 8 + 2 * j + 1) * CO + lane] = acc2[j].y;
        }
        __syncthreads();
        int r = warp;
        float v = __ldg(bias + lane);
#pragma unroll
        for (int w = 0; w < 8; ++w) v += red[(w * 8 + r) * CO + lane];
        v = fminf(fmaxf(v, 0.f), 6.f);
        xout[(size_t)(nbase + r) * ostride + lane] = v;
    }
}

// ---------------- lin1 split-K GEMM: [64,32768] x [32768,128] ----------------
__launch_bounds__(256)
__global__ void lin1_partial_kernel(const float* __restrict__ W) {
    __shared__ __align__(16) float As[64 * 32];
    __shared__ __align__(16) float Bs[32 * 128];
    int tid = threadIdx.x;
    int k0 = blockIdx.x * 128;
    int colg = tid & 31;
    int rowg = tid >> 5;
    float4 acc[8];
#pragma unroll
    for (int i = 0; i < 8; ++i) acc[i] = make_float4(0.f, 0.f, 0.f, 0.f);

    for (int ch = 0; ch < 4; ++ch) {
        int kb = k0 + ch * 32;
        for (int idx = tid; idx < 64 * 32; idx += 256) {
            int b = idx >> 5, kk = idx & 31;
            As[idx] = g_h5[(size_t)b * 32768 + kb + kk];
        }
        for (int idx = tid; idx < 32 * 128; idx += 256) {
            int kk = idx >> 7, c = idx & 127;
            Bs[idx] = W[(size_t)(kb + kk) * 128 + c];
        }
        __syncthreads();
        for (int kk = 0; kk < 32; ++kk) {
            float4 w = *reinterpret_cast<const float4*>(&Bs[kk * 128 + 4 * colg]);
#pragma unroll
            for (int i = 0; i < 8; ++i) {
                float a = As[(rowg + 8 * i) * 32 + kk];
                acc[i].x += a * w.x; acc[i].y += a * w.y;
                acc[i].z += a * w.z; acc[i].w += a * w.w;
            }
        }
        __syncthreads();
    }
#pragma unroll
    for (int i = 0; i < 8; ++i)
        *reinterpret_cast<float4*>(&g_part[(size_t)blockIdx.x * 8192 + (rowg + 8 * i) * 128 + 4 * colg]) = acc[i];
}

__global__ void lin2_kernel(const float* __restrict__ lin1b,
                            const float* __restrict__ lin2W, const float* __restrict__ lin2b,
                            float* __restrict__ out) {
    __shared__ float h[128];
    int b = blockIdx.x, c = threadIdx.x;
    float s = 0.f;
    for (int sp = 0; sp < 256; ++sp) s += g_part[(size_t)sp * 8192 + b * 128 + c];
    s += lin1b[c];
    h[c] = fmaxf(s, 0.f);
    __syncthreads();
    if (c < 3) {
        float o = lin2b[c];
#pragma unroll 4
        for (int i = 0; i < 128; ++i) o += h[i] * lin2W[i * 3 + c];
        out[b * 3 + c] = o;
    }
}

// ---------------- host ----------------
extern "C" void kernel_launch(void* const* d_in, const int* in_sizes, int n_in,
                              void* d_out, int out_size) {
    const float* x    = (const float*)d_in[0];
    const int*   ei   = (const int*)d_in[1];     // int32 (JAX x64 disabled)
    const float* pos  = (const float*)d_in[2];
    const float* enc0_W = (const float*)d_in[4],  *enc0_R = (const float*)d_in[5],  *enc0_b = (const float*)d_in[6];
    const float* enc1_W = (const float*)d_in[7],  *enc1_R = (const float*)d_in[8],  *enc1_b = (const float*)d_in[9];
    const float* enc2_W = (const float*)d_in[10], *enc2_R = (const float*)d_in[11], *enc2_b = (const float*)d_in[12];
    const float* dec0_W = (const float*)d_in[13], *dec0_R = (const float*)d_in[14], *dec0_b = (const float*)d_in[15];
    const float* dec1_W = (const float*)d_in[16], *dec1_R = (const float*)d_in[17], *dec1_b = (const float*)d_in[18];
    const float* lin1_W = (const float*)d_in[19], *lin1_b = (const float*)d_in[20];
    const float* lin2_W = (const float*)d_in[21], *lin2_b = (const float*)d_in[22];
    float* out = (float*)d_out;

    count_kernel<<<(N_EDGES + 255) / 256, 256>>>(ei);
    scan_kernel<<<1, 1024>>>();
    fill_kernel<<<(N_EDGES + 255) / 256, 256>>>(ei, pos);

    spline_conv_kernel<16, 32, 0><<<N_NODES / 8, 256>>>(x, enc0_W, enc0_R, enc0_b);
    spline_conv_kernel<32, 64, 1><<<N_NODES / 8, 256>>>(nullptr, enc1_W, enc1_R, enc1_b);
    spline_conv_kernel<64, 64, 2><<<N_NODES / 8, 256>>>(nullptr, enc2_W, enc2_R, enc2_b);
    spline_conv_kernel<128, 64, 3><<<N_NODES / 8, 256>>>(nullptr, dec0_W, dec0_R, dec0_b);
    spline_conv_kernel<96, 32, 4><<<N_NODES / 8, 256>>>(nullptr, dec1_W, dec1_R, dec1_b);

    lin1_partial_kernel<<<256, 256>>>(lin1_W);
    lin2_kernel<<<NGRAPH, 128>>>(lin1_b, lin2_W, lin2_b, out);
}

// round 17
// speedup vs baseline: 1.2340x; 1.2340x over previous
#include <cuda_runtime.h>
#include <cstdint>

#define N_NODES 65536
#define N_EDGES 524288
#define NGRAPH  64

// ---------------- device scratch (zero-initialized at module load) ----------------
__device__ int   g_count[N_NODES];
__device__ int   g_fill[N_NODES];
__device__ int   g_rowptr[N_NODES + 1];
__device__ int   g_ssrc[N_EDGES];
__device__ __align__(16) float g_scoef[(size_t)N_EDGES * 8];       // ba'(3),pad, bb'(3),pad
__device__ __align__(16) float g_cat0[(size_t)N_NODES * 128];      // [h3 | h2]
__device__ __align__(16) float g_cat1[(size_t)N_NODES * 96];       // [h4 | h1]
__device__ __align__(16) float g_h5[(size_t)N_NODES * 32];
__device__ __align__(16) float g_part[(size_t)256 * NGRAPH * 128];
// cached phase-1 aggregations (aggregation is linear over shared edge structure):
__device__ __align__(16) float g_Yh1[(size_t)N_NODES * 288];       // enc1's Y (9 x 32) -> dec1 tail
__device__ __align__(16) float g_Yh2[(size_t)N_NODES * 576];       // enc2's Y (9 x 64) -> dec0 tail

// ---------------- packed f32x2 ops (sm_103a) ----------------
__device__ __forceinline__ float2 ffma2(float2 a, float2 b, float2 c) {
    float2 d;
    asm("fma.rn.f32x2 %0, %1, %2, %3;"
        : "=l"(*reinterpret_cast<unsigned long long*>(&d))
        : "l"(*reinterpret_cast<unsigned long long*>(&a)),
          "l"(*reinterpret_cast<unsigned long long*>(&b)),
          "l"(*reinterpret_cast<unsigned long long*>(&c)));
    return d;
}
__device__ __forceinline__ float2 fmul2(float2 a, float2 b) {
    float2 d;
    asm("mul.rn.f32x2 %0, %1, %2;"
        : "=l"(*reinterpret_cast<unsigned long long*>(&d))
        : "l"(*reinterpret_cast<unsigned long long*>(&a)),
          "l"(*reinterpret_cast<unsigned long long*>(&b)));
    return d;
}

// ---------------- CSR build ----------------
__global__ void count_kernel(const int* __restrict__ ei) {
    int e = blockIdx.x * blockDim.x + threadIdx.x;
    if (e < N_EDGES) {
        int dst = ei[N_EDGES + e];
        if ((unsigned)dst < (unsigned)N_NODES) atomicAdd(&g_count[dst], 1);
    }
}

__global__ void scan_kernel() {
    __shared__ int ssum[1024];
    int t = threadIdx.x;
    int base = t * 64;
    int sum = 0;
    for (int j = 0; j < 64; ++j) sum += g_count[base + j];
    ssum[t] = sum;
    __syncthreads();
    for (int off = 1; off < 1024; off <<= 1) {
        int v = (t >= off) ? ssum[t - off] : 0;
        __syncthreads();
        ssum[t] += v;
        __syncthreads();
    }
    int run = ssum[t] - sum;
    for (int j = 0; j < 64; ++j) { g_rowptr[base + j] = run; run += g_count[base + j]; }
    if (t == 1023) g_rowptr[N_NODES] = run;
}

__global__ void fill_kernel(const int* __restrict__ ei, const float* __restrict__ pos) {
    int e = blockIdx.x * blockDim.x + threadIdx.x;
    if (e >= N_EDGES) return;
    int src = ei[e];
    int dst = ei[N_EDGES + e];
    if ((unsigned)src >= (unsigned)N_NODES || (unsigned)dst >= (unsigned)N_NODES) return;
    float p0 = pos[2 * e], p1 = pos[2 * e + 1];
    int   b0i = (int)floorf(p0);
    int   b1i = (int)floorf(p1);
    float f0 = p0 - (float)b0i;
    float f1 = p1 - (float)b1i;
    float ba[3] = {0.5f * (1.f - f0) * (1.f - f0), -f0 * f0 + f0 + 0.5f, 0.5f * f0 * f0};
    float bb[3] = {0.5f * (1.f - f1) * (1.f - f1), -f1 * f1 + f1 + 0.5f, 0.5f * f1 * f1};
    // clipping collapses independently per dim -> coefs stay a rank-1 outer product
    float bap[3] = {0.f, 0.f, 0.f}, bbp[3] = {0.f, 0.f, 0.f};
#pragma unroll
    for (int t = 0; t < 3; ++t) {
        bap[min(max(b0i + t, 0), 2)] += ba[t];
        bbp[min(max(b1i + t, 0), 2)] += bb[t];
    }
    int slot = g_rowptr[dst] + atomicAdd(&g_fill[dst], 1);
    g_ssrc[slot] = src;
    float* cw = g_scoef + (size_t)slot * 8;
    cw[0] = bap[0]; cw[1] = bap[1]; cw[2] = bap[2]; cw[3] = 0.f;
    cw[4] = bbp[0]; cw[5] = bbp[1]; cw[6] = bbp[2]; cw[7] = 0.f;
}

// ---------------- fused SplineConv layer (8 nodes/block) ----------------
// Phase 1: warp per node; EPW edges concurrently via lane-groups of LPE lanes; separable
//          rank-1 coefs (2 LDG.128); FFMA2 accumulate; shfl butterfly; decoders reuse
//          cached Y for the concat-tail; enc1/enc2 persist Y for decoder reuse.
// Phase 2: warp-split-K GEMM (broadcast smem y, L2-stream weights, packed FFMA2).
template <int CI, int CO, int LAYER>
__launch_bounds__(256, 4)
__global__ void spline_conv_kernel(const float* __restrict__ xext,
                                   const float* __restrict__ W,     // [9*CI][CO]
                                   const float* __restrict__ root,  // [CI][CO]
                                   const float* __restrict__ bias)  // [CO]
{
    constexpr int KT    = 9 * CI;
    constexpr int CIAGG = (LAYER >= 3) ? 64 : CI;    // decoders aggregate head 64 ch only
    constexpr int LPE   = CIAGG / 4;                 // lanes per edge: 4,8,16,16,16
    constexpr int EPW   = 32 / LPE;                  // edges per warp-iter: 8,4,2,2,2
    constexpr int SMAX  = (8 * KT > 64 * CO) ? 8 * KT : 64 * CO;

    const float* xin; float* xout; int istride, ostride;
    if constexpr (LAYER == 0)      { xin = xext;        istride = 16;  xout = g_cat1 + 64; ostride = 96;  }
    else if constexpr (LAYER == 1) { xin = g_cat1 + 64; istride = 96;  xout = g_cat0 + 64; ostride = 128; }
    else if constexpr (LAYER == 2) { xin = g_cat0 + 64; istride = 128; xout = g_cat0;      ostride = 128; }
    else if constexpr (LAYER == 3) { xin = g_cat0;      istride = 128; xout = g_cat1;      ostride = 96;  }
    else                           { xin = g_cat1;      istride = 96;  xout = g_h5;        ostride = 32;  }

    __shared__ __align__(16) float smem[SMAX + 8 * CI];
    float* Ys = smem;             // [8][KT]  (later overlaid by reduction buffer)
    float* Xs = smem + SMAX;      // [8][CI]

    int tid = threadIdx.x, lane = tid & 31, warp = tid >> 5;
    int nbase = blockIdx.x * 8;

    // Re-zero CSR scratch for the next run (dead after fill_kernel this run).
    if constexpr (LAYER == 0) {
        if (tid < 8) { g_count[nbase + tid] = 0; g_fill[nbase + tid] = 0; }
    }

    // ---- phase 1 ----
    {
        int n = nbase + warp;
        int s0 = g_rowptr[n], s1 = g_rowptr[n + 1];
        int deg = s1 - s0;
        int i_ch = lane % LPE;           // channel chunk (float4) within aggregated head
        int g    = lane / LPE;           // edge sub-slot

        float2 accp[9][2];
#pragma unroll
        for (int k = 0; k < 9; ++k) {
            accp[k][0] = make_float2(0.f, 0.f);
            accp[k][1] = make_float2(0.f, 0.f);
        }

        for (int s = s0 + g; s < s1; s += EPW) {
            int src = g_ssrc[s];
            const float4* cp = reinterpret_cast<const float4*>(g_scoef + (size_t)s * 8);
            float4 A  = cp[0];   // ba'0..2
            float4 Bq = cp[1];   // bb'0..2
            float4 X  = *reinterpret_cast<const float4*>(xin + (size_t)src * istride + 4 * i_ch);
            float2 xlo = make_float2(X.x, X.y);
            float2 xhi = make_float2(X.z, X.w);
            float2 u0l = fmul2(make_float2(Bq.x, Bq.x), xlo), u0h = fmul2(make_float2(Bq.x, Bq.x), xhi);
            float2 u1l = fmul2(make_float2(Bq.y, Bq.y), xlo), u1h = fmul2(make_float2(Bq.y, Bq.y), xhi);
            float2 u2l = fmul2(make_float2(Bq.z, Bq.z), xlo), u2h = fmul2(make_float2(Bq.z, Bq.z), xhi);
            float2 a0 = make_float2(A.x, A.x), a1 = make_float2(A.y, A.y), a2 = make_float2(A.z, A.z);
            accp[0][0] = ffma2(a0, u0l, accp[0][0]); accp[0][1] = ffma2(a0, u0h, accp[0][1]);
            accp[1][0] = ffma2(a1, u0l, accp[1][0]); accp[1][1] = ffma2(a1, u0h, accp[1][1]);
            accp[2][0] = ffma2(a2, u0l, accp[2][0]); accp[2][1] = ffma2(a2, u0h, accp[2][1]);
            accp[3][0] = ffma2(a0, u1l, accp[3][0]); accp[3][1] = ffma2(a0, u1h, accp[3][1]);
            accp[4][0] = ffma2(a1, u1l, accp[4][0]); accp[4][1] = ffma2(a1, u1h, accp[4][1]);
            accp[5][0] = ffma2(a2, u1l, accp[5][0]); accp[5][1] = ffma2(a2, u1h, accp[5][1]);
            accp[6][0] = ffma2(a0, u2l, accp[6][0]); accp[6][1] = ffma2(a0, u2h, accp[6][1]);
            accp[7][0] = ffma2(a1, u2l, accp[7][0]); accp[7][1] = ffma2(a1, u2h, accp[7][1]);
            accp[8][0] = ffma2(a2, u2l, accp[8][0]); accp[8][1] = ffma2(a2, u2h, accp[8][1]);
        }

        // cross-group butterfly (sum over edge sub-slots)
        if constexpr (EPW > 1) {
#pragma unroll
            for (int m = LPE; m < 32; m <<= 1)
#pragma unroll
                for (int k = 0; k < 9; ++k)
#pragma unroll
                    for (int h = 0; h < 2; ++h) {
                        accp[k][h].x += __shfl_xor_sync(0xffffffffu, accp[k][h].x, m);
                        accp[k][h].y += __shfl_xor_sync(0xffffffffu, accp[k][h].y, m);
                    }
        }

        float inv = 1.0f / (float)max(1, deg);
        if (g == 0) {
#pragma unroll
            for (int k = 0; k < 9; ++k) {
                float4 yv = make_float4(accp[k][0].x * inv, accp[k][0].y * inv,
                                        accp[k][1].x * inv, accp[k][1].y * inv);
                *reinterpret_cast<float4*>(&Ys[warp * KT + k * CI + 4 * i_ch]) = yv;
                if constexpr (LAYER == 1)
                    *reinterpret_cast<float4*>(&g_Yh1[(size_t)n * 288 + k * 32 + 4 * i_ch]) = yv;
                if constexpr (LAYER == 2)
                    *reinterpret_cast<float4*>(&g_Yh2[(size_t)n * 576 + k * 64 + 4 * i_ch]) = yv;
            }
        }
        // decoders: stream cached aggregation into the concat-tail channels of Ys
        if constexpr (LAYER == 3) {          // tail = h2's Y (64 ch) from enc2
            for (int idx = lane; idx < 144; idx += 32) {       // 9 * 64 / 4
                int k = idx >> 4, cq = idx & 15;
                float4 v = *reinterpret_cast<const float4*>(&g_Yh2[(size_t)n * 576 + k * 64 + 4 * cq]);
                *reinterpret_cast<float4*>(&Ys[warp * KT + k * CI + 64 + 4 * cq]) = v;
            }
        }
        if constexpr (LAYER == 4) {          // tail = h1's Y (32 ch) from enc1
            for (int idx = lane; idx < 72; idx += 32) {        // 9 * 32 / 4
                int k = idx >> 3, cq = idx & 7;
                float4 v = *reinterpret_cast<const float4*>(&g_Yh1[(size_t)n * 288 + k * 32 + 4 * cq]);
                *reinterpret_cast<float4*>(&Ys[warp * KT + k * CI + 64 + 4 * cq]) = v;
            }
        }
        if (4 * lane < CI)
            *reinterpret_cast<float4*>(&Xs[warp * CI + 4 * lane]) =
                *reinterpret_cast<const float4*>(xin + (size_t)n * istride + 4 * lane);
    }
    __syncthreads();

    // ---- phase 2: warp-split-K GEMM (measured-best form) ----
    if constexpr (CO == 64) {
        float2 acc2[8];
#pragma unroll
        for (int r = 0; r < 8; ++r) acc2[r] = make_float2(0.f, 0.f);

#pragma unroll 2
        for (int p4 = warp; p4 < KT / 4; p4 += 8) {
            int k = 4 * p4;
            float wA[4], wB[4];
#pragma unroll
            for (int i = 0; i < 4; ++i) {
                wA[i] = __ldg(W + (size_t)(k + i) * CO + lane);
                wB[i] = __ldg(W + (size_t)(k + i) * CO + lane + 32);
            }
#pragma unroll
            for (int r = 0; r < 8; ++r) {
                float4 y = *reinterpret_cast<const float4*>(&Ys[r * KT + k]);
                acc2[r] = ffma2(make_float2(y.x, y.x), make_float2(wA[0], wB[0]), acc2[r]);
                acc2[r] = ffma2(make_float2(y.y, y.y), make_float2(wA[1], wB[1]), acc2[r]);
                acc2[r] = ffma2(make_float2(y.z, y.z), make_float2(wA[2], wB[2]), acc2[r]);
                acc2[r] = ffma2(make_float2(y.w, y.w), make_float2(wA[3], wB[3]), acc2[r]);
            }
        }
#pragma unroll 2
        for (int p4 = warp; p4 < CI / 4; p4 += 8) {
            int k = 4 * p4;
            float wA[4], wB[4];
#pragma unroll
            for (int i = 0; i < 4; ++i) {
                wA[i] = __ldg(root + (size_t)(k + i) * CO + lane);
                wB[i] = __ldg(root + (size_t)(k + i) * CO + lane + 32);
            }
#pragma unroll
            for (int r = 0; r < 8; ++r) {
                float4 y = *reinterpret_cast<const float4*>(&Xs[r * CI + k]);
                acc2[r] = ffma2(make_float2(y.x, y.x), make_float2(wA[0], wB[0]), acc2[r]);
                acc2[r] = ffma2(make_float2(y.y, y.y), make_float2(wA[1], wB[1]), acc2[r]);
                acc2[r] = ffma2(make_float2(y.z, y.z), make_float2(wA[2], wB[2]), acc2[r]);
                acc2[r] = ffma2(make_float2(y.w, y.w), make_float2(wA[3], wB[3]), acc2[r]);
            }
        }
        __syncthreads();
        float* red = smem;   // [8 warps][8 rows][CO]
#pragma unroll
        for (int r = 0; r < 8; ++r) {
            red[(warp * 8 + r) * CO + lane]      = acc2[r].x;
            red[(warp * 8 + r) * CO + lane + 32] = acc2[r].y;
        }
        __syncthreads();
        int r = warp;
        float vA = __ldg(bias + lane), vB = __ldg(bias + lane + 32);
#pragma unroll
        for (int w = 0; w < 8; ++w) {
            vA += red[(w * 8 + r) * CO + lane];
            vB += red[(w * 8 + r) * CO + lane + 32];
        }
        vA = fminf(fmaxf(vA, 0.f), 6.f);
        vB = fminf(fmaxf(vB, 0.f), 6.f);
        xout[(size_t)(nbase + r) * ostride + lane]      = vA;
        xout[(size_t)(nbase + r) * ostride + lane + 32] = vB;
    } else {  // CO == 32
        float2 acc2[4];
#pragma unroll
        for (int j = 0; j < 4; ++j) acc2[j] = make_float2(0.f, 0.f);

#pragma unroll 2
        for (int p4 = warp; p4 < KT / 4; p4 += 8) {
            int k = 4 * p4;
            float w4[4];
#pragma unroll
            for (int i = 0; i < 4; ++i) w4[i] = __ldg(W + (size_t)(k + i) * CO + lane);
#pragma unroll
            for (int j = 0; j < 4; ++j) {
                float4 ya = *reinterpret_cast<const float4*>(&Ys[(2 * j) * KT + k]);
                float4 yb = *reinterpret_cast<const float4*>(&Ys[(2 * j + 1) * KT + k]);
                acc2[j] = ffma2(make_float2(ya.x, yb.x), make_float2(w4[0], w4[0]), acc2[j]);
                acc2[j] = ffma2(make_float2(ya.y, yb.y), make_float2(w4[1], w4[1]), acc2[j]);
                acc2[j] = ffma2(make_float2(ya.z, yb.z), make_float2(w4[2], w4[2]), acc2[j]);
                acc2[j] = ffma2(make_float2(ya.w, yb.w), make_float2(w4[3], w4[3]), acc2[j]);
            }
        }
#pragma unroll 2
        for (int p4 = warp; p4 < CI / 4; p4 += 8) {
            int k = 4 * p4;
            float w4[4];
#pragma unroll
            for (int i = 0; i < 4; ++i) w4[i] = __ldg(root + (size_t)(k + i) * CO + lane);
#pragma unroll
            for (int j = 0; j < 4; ++j) {
                float4 ya = *reinterpret_cast<const float4*>(&Xs[(2 * j) * CI + k]);
                float4 yb = *reinterpret_cast<const float4*>(&Xs[(2 * j + 1) * CI + k]);
                acc2[j] = ffma2(make_float2(ya.x, yb.x), make_float2(w4[0], w4[0]), acc2[j]);
                acc2[j] = ffma2(make_float2(ya.y, yb.y), make_float2(w4[1], w4[1]), acc2[j]);
                acc2[j] = ffma2(make_float2(ya.z, yb.z), make_float2(w4[2], w4[2]), acc2[j]);
                acc2[j] = ffma2(make_float2(ya.w, yb.w), make_float2(w4[3], w4[3]), acc2[j]);
            }
        }
        __syncthreads();
        float* red = smem;   // [8 warps][8 rows][CO]
#pragma unroll
        for (int j = 0; j < 4; ++j) {
            red[(warp * 8 + 2 * j) * CO + lane]     = acc2[j].x;
            red[(warp * 8 + 2 * j + 1) * CO + lane] = acc2[j].y;
        }
        __syncthreads();
        int r = warp;
        float v = __ldg(bias + lane);
#pragma unroll
        for (int w = 0; w < 8; ++w) v += red[(w * 8 + r) * CO + lane];
        v = fminf(fmaxf(v, 0.f), 6.f);
        xout[(size_t)(nbase + r) * ostride + lane] = v;
    }
}

// ---------------- lin1 split-K GEMM: [64,32768] x [32768,128] ----------------
__launch_bounds__(256)
__global__ void lin1_partial_kernel(const float* __restrict__ W) {
    __shared__ __align__(16) float As[64 * 32];
    __shared__ __align__(16) float Bs[32 * 128];
    int tid = threadIdx.x;
    int k0 = blockIdx.x * 128;
    int colg = tid & 31;
    int rowg = tid >> 5;
    float4 acc[8];
#pragma unroll
    for (int i = 0; i < 8; ++i) acc[i] = make_float4(0.f, 0.f, 0.f, 0.f);

    for (int ch = 0; ch < 4; ++ch) {
        int kb = k0 + ch * 32;
        for (int idx = tid; idx < 64 * 32; idx += 256) {
            int b = idx >> 5, kk = idx & 31;
            As[idx] = g_h5[(size_t)b * 32768 + kb + kk];
        }
        for (int idx = tid; idx < 32 * 128; idx += 256) {
            int kk = idx >> 7, c = idx & 127;
            Bs[idx] = W[(size_t)(kb + kk) * 128 + c];
        }
        __syncthreads();
        for (int kk = 0; kk < 32; ++kk) {
            float4 w = *reinterpret_cast<const float4*>(&Bs[kk * 128 + 4 * colg]);
#pragma unroll
            for (int i = 0; i < 8; ++i) {
                float a = As[(rowg + 8 * i) * 32 + kk];
                acc[i].x += a * w.x; acc[i].y += a * w.y;
                acc[i].z += a * w.z; acc[i].w += a * w.w;
            }
        }
        __syncthreads();
    }
#pragma unroll
    for (int i = 0; i < 8; ++i)
        *reinterpret_cast<float4*>(&g_part[(size_t)blockIdx.x * 8192 + (rowg + 8 * i) * 128 + 4 * colg]) = acc[i];
}

__global__ void lin2_kernel(const float* __restrict__ lin1b,
                            const float* __restrict__ lin2W, const float* __restrict__ lin2b,
                            float* __restrict__ out) {
    __shared__ float h[128];
    int b = blockIdx.x, c = threadIdx.x;
    float s = 0.f;
    for (int sp = 0; sp < 256; ++sp) s += g_part[(size_t)sp * 8192 + b * 128 + c];
    s += lin1b[c];
    h[c] = fmaxf(s, 0.f);
    __syncthreads();
    if (c < 3) {
        float o = lin2b[c];
#pragma unroll 4
        for (int i = 0; i < 128; ++i) o += h[i] * lin2W[i * 3 + c];
        out[b * 3 + c] = o;
    }
}

// ---------------- host ----------------
extern "C" void kernel_launch(void* const* d_in, const int* in_sizes, int n_in,
                              void* d_out, int out_size) {
    const float* x    = (const float*)d_in[0];
    const int*   ei   = (const int*)d_in[1];     // int32 (JAX x64 disabled)
    const float* pos  = (const float*)d_in[2];
    const float* enc0_W = (const float*)d_in[4],  *enc0_R = (const float*)d_in[5],  *enc0_b = (const float*)d_in[6];
    const float* enc1_W = (const float*)d_in[7],  *enc1_R = (const float*)d_in[8],  *enc1_b = (const float*)d_in[9];
    const float* enc2_W = (const float*)d_in[10], *enc2_R = (const float*)d_in[11], *enc2_b = (const float*)d_in[12];
    const float* dec0_W = (const float*)d_in[13], *dec0_R = (const float*)d_in[14], *dec0_b = (const float*)d_in[15];
    const float* dec1_W = (const float*)d_in[16], *dec1_R = (const float*)d_in[17], *dec1_b = (const float*)d_in[18];
    const float* lin1_W = (const float*)d_in[19], *lin1_b = (const float*)d_in[20];
    const float* lin2_W = (const float*)d_in[21], *lin2_b = (const float*)d_in[22];
    float* out = (float*)d_out;

    count_kernel<<<(N_EDGES + 255) / 256, 256>>>(ei);
    scan_kernel<<<1, 1024>>>();
    fill_kernel<<<(N_EDGES + 255) / 256, 256>>>(ei, pos);

    spline_conv_kernel<16, 32, 0><<<N_NODES / 8, 256>>>(x, enc0_W, enc0_R, enc0_b);
    spline_conv_kernel<32, 64, 1><<<N_NODES / 8, 256>>>(nullptr, enc1_W, enc1_R, enc1_b);
    spline_conv_kernel<64, 64, 2><<<N_NODES / 8, 256>>>(nullptr, enc2_W, enc2_R, enc2_b);
    spline_conv_kernel<128, 64, 3><<<N_NODES / 8, 256>>>(nullptr, dec0_W, dec0_R, dec0_b);
    spline_conv_kernel<96, 32, 4><<<N_NODES / 8, 256>>>(nullptr, dec1_W, dec1_R, dec1_b);

    lin1_partial_kernel<<<256, 256>>>(lin1_W);
    lin2_kernel<<<NGRAPH, 128>>>(lin1_b, lin2_W, lin2_b, out);
}